// round 12
// baseline (speedup 1.0000x reference)
#include <cuda_runtime.h>

#define BZ 32
#define MZ 8192
#define DZ 256
#define NCHUNK 32
#define TOKS (MZ / NCHUNK)            // 256 tokens per chunk
#define WARPS 8
#define TOKS_PER_WARP (TOKS / WARPS)  // 32
#define NSLICE 8
#define ATTN_SCALE 0.0625f            // 1/sqrt(256)

// Scratch (no allocations allowed in kernel_launch)
__device__ float  g_part[BZ * NSLICE * DZ];        // qtil partials
__device__ float  g_pacc[BZ * NCHUNK * DZ];        // 1 MB
__device__ float2 g_pmz[BZ * NCHUNK];              // (max, Z) per chunk
__device__ int    g_done[BZ];                      // zero-init; self-resetting

#define DOT8(xa, xb) ((xa).x*qa.x + (xa).y*qa.y + (xa).z*qa.z + (xa).w*qa.w \
                    + (xb).x*qb.x + (xb).y*qb.y + (xb).z*qb.z + (xb).w*qb.w)

#define DOT8T(xa, xb) ((xa).x*ta.x + (xa).y*ta.y + (xa).z*ta.z + (xa).w*ta.w \
                     + (xb).x*tb.x + (xb).y*tb.y + (xb).z*tb.z + (xb).w*tb.w)

// ---------------------------------------------------------------------------
// Kernel A: partial q~ per (batch, j-slice).  Block (b,s), 256 blocks.
// Calls the PDL trigger at entry so kernel B can launch concurrently.
// ---------------------------------------------------------------------------
__global__ void __launch_bounds__(256) qtil_partial(
    const float* __restrict__ query,
    const float* __restrict__ q_w,
    const float* __restrict__ q_b,
    const float* __restrict__ k_w)
{
    cudaTriggerProgrammaticLaunchCompletion();

    const int b    = blockIdx.x >> 3;
    const int s    = blockIdx.x & 7;
    const int tid  = threadIdx.x;
    const int w    = tid >> 5;
    const int lane = tid & 31;

    __shared__ float part[WARPS][DZ];

    const float4* qv = (const float4*)(query + (size_t)b * DZ);
    const float4 qa = qv[lane];
    const float4 qb = qv[32 + lane];

    const int j0 = s * 32 + w * 4;

    const float4* r0 = (const float4*)(q_w + (size_t)(j0 + 0) * DZ);
    const float4* r1 = (const float4*)(q_w + (size_t)(j0 + 1) * DZ);
    const float4* r2 = (const float4*)(q_w + (size_t)(j0 + 2) * DZ);
    const float4* r3 = (const float4*)(q_w + (size_t)(j0 + 3) * DZ);
    const float4* k0 = (const float4*)(k_w + (size_t)(j0 + 0) * DZ);
    const float4* k1 = (const float4*)(k_w + (size_t)(j0 + 1) * DZ);
    const float4* k2 = (const float4*)(k_w + (size_t)(j0 + 2) * DZ);
    const float4* k3 = (const float4*)(k_w + (size_t)(j0 + 3) * DZ);
    const float4 a0 = r0[lane], b0 = r0[32 + lane];
    const float4 a1 = r1[lane], b1 = r1[32 + lane];
    const float4 a2 = r2[lane], b2 = r2[32 + lane];
    const float4 a3 = r3[lane], b3 = r3[32 + lane];
    const float4 w0a = k0[lane], w0b = k0[32 + lane];
    const float4 w1a = k1[lane], w1b = k1[32 + lane];
    const float4 w2a = k2[lane], w2b = k2[32 + lane];
    const float4 w3a = k3[lane], w3b = k3[32 + lane];

    float d0 = DOT8(a0, b0);
    float d1 = DOT8(a1, b1);
    float d2 = DOT8(a2, b2);
    float d3 = DOT8(a3, b3);
    #pragma unroll
    for (int o = 16; o > 0; o >>= 1) {
        d0 += __shfl_xor_sync(0xffffffffu, d0, o);
        d1 += __shfl_xor_sync(0xffffffffu, d1, o);
        d2 += __shfl_xor_sync(0xffffffffu, d2, o);
        d3 += __shfl_xor_sync(0xffffffffu, d3, o);
    }
    const float qr0 = d0 + __ldg(q_b + j0 + 0);
    const float qr1 = d1 + __ldg(q_b + j0 + 1);
    const float qr2 = d2 + __ldg(q_b + j0 + 2);
    const float qr3 = d3 + __ldg(q_b + j0 + 3);

    float4 pa, pb;
    pa.x = qr0 * w0a.x + qr1 * w1a.x + qr2 * w2a.x + qr3 * w3a.x;
    pa.y = qr0 * w0a.y + qr1 * w1a.y + qr2 * w2a.y + qr3 * w3a.y;
    pa.z = qr0 * w0a.z + qr1 * w1a.z + qr2 * w2a.z + qr3 * w3a.z;
    pa.w = qr0 * w0a.w + qr1 * w1a.w + qr2 * w2a.w + qr3 * w3a.w;
    pb.x = qr0 * w0b.x + qr1 * w1b.x + qr2 * w2b.x + qr3 * w3b.x;
    pb.y = qr0 * w0b.y + qr1 * w1b.y + qr2 * w2b.y + qr3 * w3b.y;
    pb.z = qr0 * w0b.z + qr1 * w1b.z + qr2 * w2b.z + qr3 * w3b.z;
    pb.w = qr0 * w0b.w + qr1 * w1b.w + qr2 * w2b.w + qr3 * w3b.w;

    *(float4*)(&part[w][lane * 4])       = pa;
    *(float4*)(&part[w][128 + lane * 4]) = pb;
    __syncthreads();

    float acc = 0.0f;
    #pragma unroll
    for (int i = 0; i < WARPS; i++) acc += part[i][tid];
    g_part[(b * NSLICE + s) * DZ + tid] = acc;
}

// ---------------------------------------------------------------------------
// Kernel B: streaming pass + fused finalize (former kernel C).
// ---------------------------------------------------------------------------
#define ACC8(p, xa, xb)                                                    \
    do {                                                                   \
        aa.x += (p) * (xa).x; aa.y += (p) * (xa).y;                        \
        aa.z += (p) * (xa).z; aa.w += (p) * (xa).w;                        \
        ab.x += (p) * (xb).x; ab.y += (p) * (xb).y;                        \
        ab.z += (p) * (xb).z; ab.w += (p) * (xb).w;                        \
    } while (0)

#define LOADG8(g)                                                          \
    do {                                                                   \
        const float4* tp = base + (size_t)(g) * 8 * (DZ / 4);              \
        xa0 = __ldcs(tp + lane);        xb0 = __ldcs(tp + 32 + lane);      \
        xa1 = __ldcs(tp + 64 + lane);   xb1 = __ldcs(tp + 96 + lane);      \
        xa2 = __ldcs(tp + 128 + lane);  xb2 = __ldcs(tp + 160 + lane);     \
        xa3 = __ldcs(tp + 192 + lane);  xb3 = __ldcs(tp + 224 + lane);     \
        xa4 = __ldcs(tp + 256 + lane);  xb4 = __ldcs(tp + 288 + lane);     \
        xa5 = __ldcs(tp + 320 + lane);  xb5 = __ldcs(tp + 352 + lane);     \
        xa6 = __ldcs(tp + 384 + lane);  xb6 = __ldcs(tp + 416 + lane);     \
        xa7 = __ldcs(tp + 448 + lane);  xb7 = __ldcs(tp + 480 + lane);     \
    } while (0)

#define PROCG8()                                                           \
    do {                                                                   \
        float d0 = DOT8(xa0, xb0);                                         \
        float d1 = DOT8(xa1, xb1);                                         \
        float d2 = DOT8(xa2, xb2);                                         \
        float d3 = DOT8(xa3, xb3);                                         \
        float d4 = DOT8(xa4, xb4);                                         \
        float d5 = DOT8(xa5, xb5);                                         \
        float d6 = DOT8(xa6, xb6);                                         \
        float d7 = DOT8(xa7, xb7);                                         \
        _Pragma("unroll")                                                  \
        for (int o = 16; o > 0; o >>= 1) {                                 \
            d0 += __shfl_xor_sync(0xffffffffu, d0, o);                     \
            d1 += __shfl_xor_sync(0xffffffffu, d1, o);                     \
            d2 += __shfl_xor_sync(0xffffffffu, d2, o);                     \
            d3 += __shfl_xor_sync(0xffffffffu, d3, o);                     \
            d4 += __shfl_xor_sync(0xffffffffu, d4, o);                     \
            d5 += __shfl_xor_sync(0xffffffffu, d5, o);                     \
            d6 += __shfl_xor_sync(0xffffffffu, d6, o);                     \
            d7 += __shfl_xor_sync(0xffffffffu, d7, o);                     \
        }                                                                  \
        float gm = fmaxf(fmaxf(fmaxf(d0, d1), fmaxf(d2, d3)),              \
                         fmaxf(fmaxf(d4, d5), fmaxf(d6, d7)));             \
        if (gm > m) {                                                      \
            const float corr = __expf(m - gm);                             \
            z *= corr;                                                     \
            aa.x *= corr; aa.y *= corr; aa.z *= corr; aa.w *= corr;        \
            ab.x *= corr; ab.y *= corr; ab.z *= corr; ab.w *= corr;        \
            m = gm;                                                        \
        }                                                                  \
        const float p0 = __expf(d0 - m);                                   \
        const float p1 = __expf(d1 - m);                                   \
        const float p2 = __expf(d2 - m);                                   \
        const float p3 = __expf(d3 - m);                                   \
        const float p4 = __expf(d4 - m);                                   \
        const float p5 = __expf(d5 - m);                                   \
        const float p6 = __expf(d6 - m);                                   \
        const float p7 = __expf(d7 - m);                                   \
        z += ((p0 + p1) + (p2 + p3)) + ((p4 + p5) + (p6 + p7));            \
        ACC8(p0, xa0, xb0);                                                \
        ACC8(p1, xa1, xb1);                                                \
        ACC8(p2, xa2, xb2);                                                \
        ACC8(p3, xa3, xb3);                                                \
        ACC8(p4, xa4, xb4);                                                \
        ACC8(p5, xa5, xb5);                                                \
        ACC8(p6, xa6, xb6);                                                \
        ACC8(p7, xa7, xb7);                                                \
    } while (0)

__global__ void __launch_bounds__(256) attn_pass(
    const float* __restrict__ tokens,
    const float* __restrict__ v_w,
    const float* __restrict__ v_b,
    float* __restrict__ out)
{
    const int b    = blockIdx.x >> 5;
    const int c    = blockIdx.x & 31;
    const int tid  = threadIdx.x;
    const int w    = tid >> 5;
    const int lane = tid & 31;

    __shared__ float  qtil_s[DZ];           // also t_s in finalize
    __shared__ float  sm_m[WARPS];
    __shared__ float  sm_z[WARPS];
    __shared__ float4 sm_acc[WARPS][64];
    __shared__ float2 mz_s[NCHUNK];
    __shared__ int    s_last;

    const int tok0 = c * TOKS + w * TOKS_PER_WARP;
    const float4* base = (const float4*)tokens + ((size_t)b * MZ + tok0) * (DZ / 4);

    // Prefetch group 0 (independent of kernel A) — overlaps A via PDL.
    float4 xa0, xb0, xa1, xb1, xa2, xb2, xa3, xb3;
    float4 xa4, xb4, xa5, xb5, xa6, xb6, xa7, xb7;
    LOADG8(0);

    cudaGridDependencySynchronize();        // wait for A's g_part

    {
        const float* gp = g_part + (size_t)b * NSLICE * DZ + tid;
        float t = 0.0f;
        #pragma unroll
        for (int s2 = 0; s2 < NSLICE; s2++) t += gp[s2 * DZ];
        qtil_s[tid] = t * ATTN_SCALE;
    }
    __syncthreads();

    const float4 qa = *(const float4*)(qtil_s + lane * 4);
    const float4 qb = *(const float4*)(qtil_s + 128 + lane * 4);

    float  m = -1e30f, z = 0.0f;
    float4 aa = make_float4(0.f, 0.f, 0.f, 0.f);
    float4 ab = make_float4(0.f, 0.f, 0.f, 0.f);

    PROCG8();                               // group 0 (prefetched)
    #pragma unroll
    for (int g = 1; g < TOKS_PER_WARP / 8; g++) {
        LOADG8(g);
        PROCG8();
    }

    // Block combine -> per-chunk partial.
    if (lane == 0) { sm_m[w] = m; sm_z[w] = z; }
    sm_acc[w][lane]      = aa;
    sm_acc[w][32 + lane] = ab;
    __syncthreads();

    float Ms = sm_m[0];
    #pragma unroll
    for (int i = 1; i < WARPS; i++) Ms = fmaxf(Ms, sm_m[i]);

    const float* sa = (const float*)sm_acc;
    float accd = 0.0f;
    #pragma unroll
    for (int i = 0; i < WARPS; i++)
        accd += sa[i * DZ + tid] * __expf(sm_m[i] - Ms);
    g_pacc[((size_t)b * NCHUNK + c) * DZ + tid] = accd;

    if (tid == 0) {
        float zt = 0.0f;
        #pragma unroll
        for (int i = 0; i < WARPS; i++) zt += sm_z[i] * __expf(sm_m[i] - Ms);
        g_pmz[b * NCHUNK + c] = make_float2(Ms, zt);
    }

    // Completion gate: last-finishing block of batch b runs finalize inline.
    __threadfence();
    __syncthreads();
    if (tid == 0) s_last = (atomicAdd(&g_done[b], 1) == NCHUNK - 1) ? 1 : 0;
    __syncthreads();
    if (!s_last) return;

    if (tid < NCHUNK) mz_s[tid] = __ldcg(&g_pmz[b * NCHUNK + tid]);
    __syncthreads();

    float Mg = mz_s[0].x;
    #pragma unroll
    for (int i = 1; i < NCHUNK; i++) Mg = fmaxf(Mg, mz_s[i].x);
    float Zg = 0.0f;
    #pragma unroll
    for (int i = 0; i < NCHUNK; i++) Zg += mz_s[i].y * __expf(mz_s[i].x - Mg);
    const float inv = 1.0f / Zg;

    float td = 0.0f;
    #pragma unroll 8
    for (int i = 0; i < NCHUNK; i++)
        td += __ldcg(&g_pacc[((size_t)b * NCHUNK + i) * DZ + tid])
            * __expf(mz_s[i].x - Mg);
    __syncthreads();                        // before qtil_s reuse
    qtil_s[tid] = td * inv;                 // t[b, tid]
    __syncthreads();

    const float4 ta = *(const float4*)(qtil_s + lane * 4);
    const float4 tb = *(const float4*)(qtil_s + 128 + lane * 4);

    #pragma unroll
    for (int g = 0; g < 8; g++) {
        const int j0 = w * 32 + g * 4;
        const float4* r0 = (const float4*)(v_w + (size_t)(j0 + 0) * DZ);
        const float4* r1 = (const float4*)(v_w + (size_t)(j0 + 1) * DZ);
        const float4* r2 = (const float4*)(v_w + (size_t)(j0 + 2) * DZ);
        const float4* r3 = (const float4*)(v_w + (size_t)(j0 + 3) * DZ);
        const float4 a0 = r0[lane], b0 = r0[32 + lane];
        const float4 a1 = r1[lane], b1 = r1[32 + lane];
        const float4 a2 = r2[lane], b2 = r2[32 + lane];
        const float4 a3 = r3[lane], b3 = r3[32 + lane];
        float e0 = DOT8T(a0, b0);
        float e1 = DOT8T(a1, b1);
        float e2 = DOT8T(a2, b2);
        float e3 = DOT8T(a3, b3);
        #pragma unroll
        for (int o = 16; o > 0; o >>= 1) {
            e0 += __shfl_xor_sync(0xffffffffu, e0, o);
            e1 += __shfl_xor_sync(0xffffffffu, e1, o);
            e2 += __shfl_xor_sync(0xffffffffu, e2, o);
            e3 += __shfl_xor_sync(0xffffffffu, e3, o);
        }
        if (lane < 4) {
            const float v = (lane == 0) ? e0 : (lane == 1) ? e1
                          : (lane == 2) ? e2 : e3;
            out[b * DZ + j0 + lane] = v + __ldg(v_b + j0 + lane);
        }
    }

    __syncthreads();
    if (tid == 0) g_done[b] = 0;            // self-reset for next replay
}

// ---------------------------------------------------------------------------
// Inputs: 0 query, 1 tokens, 2 q_w, 3 q_b, 4 k_w, 5 k_b (unused), 6 v_w, 7 v_b
// ---------------------------------------------------------------------------
extern "C" void kernel_launch(void* const* d_in, const int* in_sizes, int n_in,
                              void* d_out, int out_size)
{
    const float* query  = (const float*)d_in[0];
    const float* tokens = (const float*)d_in[1];
    const float* q_w    = (const float*)d_in[2];
    const float* q_b    = (const float*)d_in[3];
    const float* k_w    = (const float*)d_in[4];
    const float* v_w    = (const float*)d_in[6];
    const float* v_b    = (const float*)d_in[7];
    float* out = (float*)d_out;

    qtil_partial<<<BZ * NSLICE, 256>>>(query, q_w, q_b, k_w);

    cudaLaunchConfig_t cfg = {};
    cfg.gridDim  = dim3(BZ * NCHUNK, 1, 1);
    cfg.blockDim = dim3(256, 1, 1);
    cfg.dynamicSmemBytes = 0;
    cfg.stream = 0;
    cudaLaunchAttribute attrs[1];
    attrs[0].id = cudaLaunchAttributeProgrammaticStreamSerialization;
    attrs[0].val.programmaticStreamSerializationAllowed = 1;
    cfg.attrs = attrs;
    cfg.numAttrs = 1;
    cudaLaunchKernelEx(&cfg, attn_pass, tokens, v_w, v_b, out);
}

// round 13
// speedup vs baseline: 1.1471x; 1.1471x over previous
#include <cuda_runtime.h>

#define BZ 32
#define MZ 8192
#define DZ 256
#define NCHUNK 32
#define TOKS (MZ / NCHUNK)            // 256 tokens per chunk
#define WARPS 8
#define TOKS_PER_WARP (TOKS / WARPS)  // 32
#define NSLICE 8
#define ATTN_SCALE 0.0625f            // 1/sqrt(256)
#define PF_TOKS 8                     // tokens prefetched per warp via cp.async
#define TOKBUF_BYTES (WARPS * PF_TOKS * DZ * 4)   // 64 KB dynamic smem

// Scratch (no allocations allowed in kernel_launch)
__device__ float  g_part[BZ * NSLICE * DZ];
__device__ float  g_pacc[BZ * NCHUNK * DZ];
__device__ float2 g_pmz[BZ * NCHUNK];

#define DOT8(xa, xb) ((xa).x*qa.x + (xa).y*qa.y + (xa).z*qa.z + (xa).w*qa.w \
                    + (xb).x*qb.x + (xb).y*qb.y + (xb).z*qb.z + (xb).w*qb.w)

#define DOT8T(xa, xb) ((xa).x*ta.x + (xa).y*ta.y + (xa).z*ta.z + (xa).w*ta.w \
                     + (xb).x*tb.x + (xb).y*tb.y + (xb).z*tb.z + (xb).w*tb.w)

// ---------------------------------------------------------------------------
// Kernel A: partial q~ per (batch, j-slice). Triggers PDL at entry so B
// launches concurrently and its cp.async prefetch overlaps A's execution.
// ---------------------------------------------------------------------------
__global__ void __launch_bounds__(256) qtil_partial(
    const float* __restrict__ query,
    const float* __restrict__ q_w,
    const float* __restrict__ q_b,
    const float* __restrict__ k_w)
{
    cudaTriggerProgrammaticLaunchCompletion();

    const int b    = blockIdx.x >> 3;
    const int s    = blockIdx.x & 7;
    const int tid  = threadIdx.x;
    const int w    = tid >> 5;
    const int lane = tid & 31;

    __shared__ float part[WARPS][DZ];

    const float4* qv = (const float4*)(query + (size_t)b * DZ);
    const float4 qa = qv[lane];
    const float4 qb = qv[32 + lane];

    const int j0 = s * 32 + w * 4;

    const float4* r0 = (const float4*)(q_w + (size_t)(j0 + 0) * DZ);
    const float4* r1 = (const float4*)(q_w + (size_t)(j0 + 1) * DZ);
    const float4* r2 = (const float4*)(q_w + (size_t)(j0 + 2) * DZ);
    const float4* r3 = (const float4*)(q_w + (size_t)(j0 + 3) * DZ);
    const float4* k0 = (const float4*)(k_w + (size_t)(j0 + 0) * DZ);
    const float4* k1 = (const float4*)(k_w + (size_t)(j0 + 1) * DZ);
    const float4* k2 = (const float4*)(k_w + (size_t)(j0 + 2) * DZ);
    const float4* k3 = (const float4*)(k_w + (size_t)(j0 + 3) * DZ);
    const float4 a0 = r0[lane], b0 = r0[32 + lane];
    const float4 a1 = r1[lane], b1 = r1[32 + lane];
    const float4 a2 = r2[lane], b2 = r2[32 + lane];
    const float4 a3 = r3[lane], b3 = r3[32 + lane];
    const float4 w0a = k0[lane], w0b = k0[32 + lane];
    const float4 w1a = k1[lane], w1b = k1[32 + lane];
    const float4 w2a = k2[lane], w2b = k2[32 + lane];
    const float4 w3a = k3[lane], w3b = k3[32 + lane];

    float d0 = DOT8(a0, b0);
    float d1 = DOT8(a1, b1);
    float d2 = DOT8(a2, b2);
    float d3 = DOT8(a3, b3);
    #pragma unroll
    for (int o = 16; o > 0; o >>= 1) {
        d0 += __shfl_xor_sync(0xffffffffu, d0, o);
        d1 += __shfl_xor_sync(0xffffffffu, d1, o);
        d2 += __shfl_xor_sync(0xffffffffu, d2, o);
        d3 += __shfl_xor_sync(0xffffffffu, d3, o);
    }
    const float qr0 = d0 + __ldg(q_b + j0 + 0);
    const float qr1 = d1 + __ldg(q_b + j0 + 1);
    const float qr2 = d2 + __ldg(q_b + j0 + 2);
    const float qr3 = d3 + __ldg(q_b + j0 + 3);

    float4 pa, pb;
    pa.x = qr0 * w0a.x + qr1 * w1a.x + qr2 * w2a.x + qr3 * w3a.x;
    pa.y = qr0 * w0a.y + qr1 * w1a.y + qr2 * w2a.y + qr3 * w3a.y;
    pa.z = qr0 * w0a.z + qr1 * w1a.z + qr2 * w2a.z + qr3 * w3a.z;
    pa.w = qr0 * w0a.w + qr1 * w1a.w + qr2 * w2a.w + qr3 * w3a.w;
    pb.x = qr0 * w0b.x + qr1 * w1b.x + qr2 * w2b.x + qr3 * w3b.x;
    pb.y = qr0 * w0b.y + qr1 * w1b.y + qr2 * w2b.y + qr3 * w3b.y;
    pb.z = qr0 * w0b.z + qr1 * w1b.z + qr2 * w2b.z + qr3 * w3b.z;
    pb.w = qr0 * w0b.w + qr1 * w1b.w + qr2 * w2b.w + qr3 * w3b.w;

    *(float4*)(&part[w][lane * 4])       = pa;
    *(float4*)(&part[w][128 + lane * 4]) = pb;
    __syncthreads();

    float acc = 0.0f;
    #pragma unroll
    for (int i = 0; i < WARPS; i++) acc += part[i][tid];
    g_part[(b * NSLICE + s) * DZ + tid] = acc;
}

// ---------------------------------------------------------------------------
// Kernel B: streaming pass (proven R6 mainloop). PDL prologue: issue 8
// tokens/warp of cp.async into smem (register-free), then grid-sync on A.
// The DMA runs during the wait, so group 0 is already in smem when we start.
// ---------------------------------------------------------------------------
#define ACC8(p, xa, xb)                                                    \
    do {                                                                   \
        aa.x += (p) * (xa).x; aa.y += (p) * (xa).y;                        \
        aa.z += (p) * (xa).z; aa.w += (p) * (xa).w;                        \
        ab.x += (p) * (xb).x; ab.y += (p) * (xb).y;                        \
        ab.z += (p) * (xb).z; ab.w += (p) * (xb).w;                        \
    } while (0)

#define LOADG8(g)                                                          \
    do {                                                                   \
        const float4* tp = base + (size_t)(g) * 8 * (DZ / 4);              \
        xa0 = __ldcs(tp + lane);        xb0 = __ldcs(tp + 32 + lane);      \
        xa1 = __ldcs(tp + 64 + lane);   xb1 = __ldcs(tp + 96 + lane);      \
        xa2 = __ldcs(tp + 128 + lane);  xb2 = __ldcs(tp + 160 + lane);     \
        xa3 = __ldcs(tp + 192 + lane);  xb3 = __ldcs(tp + 224 + lane);     \
        xa4 = __ldcs(tp + 256 + lane);  xb4 = __ldcs(tp + 288 + lane);     \
        xa5 = __ldcs(tp + 320 + lane);  xb5 = __ldcs(tp + 352 + lane);     \
        xa6 = __ldcs(tp + 384 + lane);  xb6 = __ldcs(tp + 416 + lane);     \
        xa7 = __ldcs(tp + 448 + lane);  xb7 = __ldcs(tp + 480 + lane);     \
    } while (0)

#define LOADS8()                                                           \
    do {                                                                   \
        xa0 = wbuf[lane];        xb0 = wbuf[32 + lane];                    \
        xa1 = wbuf[64 + lane];   xb1 = wbuf[96 + lane];                    \
        xa2 = wbuf[128 + lane];  xb2 = wbuf[160 + lane];                   \
        xa3 = wbuf[192 + lane];  xb3 = wbuf[224 + lane];                   \
        xa4 = wbuf[256 + lane];  xb4 = wbuf[288 + lane];                   \
        xa5 = wbuf[320 + lane];  xb5 = wbuf[352 + lane];                   \
        xa6 = wbuf[384 + lane];  xb6 = wbuf[416 + lane];                   \
        xa7 = wbuf[448 + lane];  xb7 = wbuf[480 + lane];                   \
    } while (0)

#define PROCG8()                                                           \
    do {                                                                   \
        float d0 = DOT8(xa0, xb0);                                         \
        float d1 = DOT8(xa1, xb1);                                         \
        float d2 = DOT8(xa2, xb2);                                         \
        float d3 = DOT8(xa3, xb3);                                         \
        float d4 = DOT8(xa4, xb4);                                         \
        float d5 = DOT8(xa5, xb5);                                         \
        float d6 = DOT8(xa6, xb6);                                         \
        float d7 = DOT8(xa7, xb7);                                         \
        _Pragma("unroll")                                                  \
        for (int o = 16; o > 0; o >>= 1) {                                 \
            d0 += __shfl_xor_sync(0xffffffffu, d0, o);                     \
            d1 += __shfl_xor_sync(0xffffffffu, d1, o);                     \
            d2 += __shfl_xor_sync(0xffffffffu, d2, o);                     \
            d3 += __shfl_xor_sync(0xffffffffu, d3, o);                     \
            d4 += __shfl_xor_sync(0xffffffffu, d4, o);                     \
            d5 += __shfl_xor_sync(0xffffffffu, d5, o);                     \
            d6 += __shfl_xor_sync(0xffffffffu, d6, o);                     \
            d7 += __shfl_xor_sync(0xffffffffu, d7, o);                     \
        }                                                                  \
        float gm = fmaxf(fmaxf(fmaxf(d0, d1), fmaxf(d2, d3)),              \
                         fmaxf(fmaxf(d4, d5), fmaxf(d6, d7)));             \
        if (gm > m) {                                                      \
            const float corr = __expf(m - gm);                             \
            z *= corr;                                                     \
            aa.x *= corr; aa.y *= corr; aa.z *= corr; aa.w *= corr;        \
            ab.x *= corr; ab.y *= corr; ab.z *= corr; ab.w *= corr;        \
            m = gm;                                                        \
        }                                                                  \
        const float p0 = __expf(d0 - m);                                   \
        const float p1 = __expf(d1 - m);                                   \
        const float p2 = __expf(d2 - m);                                   \
        const float p3 = __expf(d3 - m);                                   \
        const float p4 = __expf(d4 - m);                                   \
        const float p5 = __expf(d5 - m);                                   \
        const float p6 = __expf(d6 - m);                                   \
        const float p7 = __expf(d7 - m);                                   \
        z += ((p0 + p1) + (p2 + p3)) + ((p4 + p5) + (p6 + p7));            \
        ACC8(p0, xa0, xb0);                                                \
        ACC8(p1, xa1, xb1);                                                \
        ACC8(p2, xa2, xb2);                                                \
        ACC8(p3, xa3, xb3);                                                \
        ACC8(p4, xa4, xb4);                                                \
        ACC8(p5, xa5, xb5);                                                \
        ACC8(p6, xa6, xb6);                                                \
        ACC8(p7, xa7, xb7);                                                \
    } while (0)

__global__ void __launch_bounds__(256) attn_pass(const float* __restrict__ tokens)
{
    cudaTriggerProgrammaticLaunchCompletion();   // let C launch + prefetch v_w

    extern __shared__ float4 tokbuf[];           // 64 KB dynamic

    const int b    = blockIdx.x >> 5;
    const int c    = blockIdx.x & 31;
    const int tid  = threadIdx.x;
    const int w    = tid >> 5;
    const int lane = tid & 31;

    __shared__ float  qtil_s[DZ];
    __shared__ float  sm_m[WARPS];
    __shared__ float  sm_z[WARPS];
    __shared__ float4 sm_acc[WARPS][64];

    const int tok0 = c * TOKS + w * TOKS_PER_WARP;
    const float4* base = (const float4*)tokens + ((size_t)b * MZ + tok0) * (DZ / 4);

    // Register-free prefetch of tokens 0..7 (8 KB/warp) via cp.async;
    // the DMA progresses while we wait for kernel A below.
    float4* wbuf = tokbuf + w * (PF_TOKS * DZ / 4);
    #pragma unroll
    for (int k2 = 0; k2 < (PF_TOKS * DZ / 4) / 32; k2++) {
        const int idx = lane + 32 * k2;
        const unsigned daddr = (unsigned)__cvta_generic_to_shared(wbuf + idx);
        asm volatile("cp.async.cg.shared.global [%0], [%1], 16;\n"
                     :: "r"(daddr), "l"(base + idx) : "memory");
    }
    asm volatile("cp.async.commit_group;\n" ::: "memory");

    cudaGridDependencySynchronize();             // wait for A's g_part

    {
        const float* gp = g_part + (size_t)b * NSLICE * DZ + tid;
        float t = 0.0f;
        #pragma unroll
        for (int s2 = 0; s2 < NSLICE; s2++) t += gp[s2 * DZ];
        qtil_s[tid] = t * ATTN_SCALE;
    }
    asm volatile("cp.async.wait_group 0;\n" ::: "memory");
    __syncthreads();    // one barrier: qtil_s visible + cp.async data visible

    const float4 qa = *(const float4*)(qtil_s + lane * 4);
    const float4 qb = *(const float4*)(qtil_s + 128 + lane * 4);

    float  m = -1e30f, z = 0.0f;
    float4 aa = make_float4(0.f, 0.f, 0.f, 0.f);
    float4 ab = make_float4(0.f, 0.f, 0.f, 0.f);

    float4 xa0, xb0, xa1, xb1, xa2, xb2, xa3, xb3;
    float4 xa4, xb4, xa5, xb5, xa6, xb6, xa7, xb7;

    LOADS8();                                    // group 0 from smem
    PROCG8();
    for (int g = 1; g < TOKS_PER_WARP / 8; g++) {
        LOADG8(g);
        PROCG8();
    }

    // Combine 8 warps -> per-chunk partial.
    if (lane == 0) { sm_m[w] = m; sm_z[w] = z; }
    sm_acc[w][lane]      = aa;
    sm_acc[w][32 + lane] = ab;
    __syncthreads();

    float Ms = sm_m[0];
    #pragma unroll
    for (int i = 1; i < WARPS; i++) Ms = fmaxf(Ms, sm_m[i]);

    const float* sa = (const float*)sm_acc;
    float accd = 0.0f;
    #pragma unroll
    for (int i = 0; i < WARPS; i++)
        accd += sa[i * DZ + tid] * __expf(sm_m[i] - Ms);
    g_pacc[((size_t)b * NCHUNK + c) * DZ + tid] = accd;

    if (tid == 0) {
        float zt = 0.0f;
        #pragma unroll
        for (int i = 0; i < WARPS; i++) zt += sm_z[i] * __expf(sm_m[i] - Ms);
        g_pmz[b * NCHUNK + c] = make_float2(Ms, zt);
    }
}

// ---------------------------------------------------------------------------
// Kernel C: PDL-launched; prefetches its v_w rows into registers BEFORE the
// grid sync (v_w is independent of B), so only the merge is exposed.
// ---------------------------------------------------------------------------
__global__ void __launch_bounds__(256) finalize(
    const float* __restrict__ v_w,
    const float* __restrict__ v_b,
    float* __restrict__ out)
{
    const int b    = blockIdx.x >> 3;
    const int s    = blockIdx.x & 7;
    const int tid  = threadIdx.x;
    const int w    = tid >> 5;
    const int lane = tid & 31;

    __shared__ float  t_s[DZ];
    __shared__ float2 mz_s[NCHUNK];

    const int j0 = s * 32 + w * 4;

    // Prefetch v_w rows + bias (independent of B) — overlaps B via PDL.
    const float4* r0 = (const float4*)(v_w + (size_t)(j0 + 0) * DZ);
    const float4* r1 = (const float4*)(v_w + (size_t)(j0 + 1) * DZ);
    const float4* r2 = (const float4*)(v_w + (size_t)(j0 + 2) * DZ);
    const float4* r3 = (const float4*)(v_w + (size_t)(j0 + 3) * DZ);
    const float4 a0 = r0[lane], b0 = r0[32 + lane];
    const float4 a1 = r1[lane], b1 = r1[32 + lane];
    const float4 a2 = r2[lane], b2 = r2[32 + lane];
    const float4 a3 = r3[lane], b3 = r3[32 + lane];
    const float bias = (lane < 4) ? __ldg(v_b + j0 + lane) : 0.0f;

    cudaGridDependencySynchronize();             // wait for B's partials

    if (tid < NCHUNK) mz_s[tid] = g_pmz[b * NCHUNK + tid];
    __syncthreads();

    float Mg = mz_s[0].x;
    #pragma unroll
    for (int i = 1; i < NCHUNK; i++) Mg = fmaxf(Mg, mz_s[i].x);

    float Zg = 0.0f;
    #pragma unroll
    for (int i = 0; i < NCHUNK; i++) Zg += mz_s[i].y * __expf(mz_s[i].x - Mg);
    const float inv = 1.0f / Zg;

    float td = 0.0f;
    #pragma unroll 8
    for (int i = 0; i < NCHUNK; i++)
        td += g_pacc[((size_t)b * NCHUNK + i) * DZ + tid] * __expf(mz_s[i].x - Mg);
    t_s[tid] = td * inv;
    __syncthreads();

    const float4 ta = *(const float4*)(t_s + lane * 4);
    const float4 tb = *(const float4*)(t_s + 128 + lane * 4);

    float e0 = DOT8T(a0, b0);
    float e1 = DOT8T(a1, b1);
    float e2 = DOT8T(a2, b2);
    float e3 = DOT8T(a3, b3);
    #pragma unroll
    for (int o = 16; o > 0; o >>= 1) {
        e0 += __shfl_xor_sync(0xffffffffu, e0, o);
        e1 += __shfl_xor_sync(0xffffffffu, e1, o);
        e2 += __shfl_xor_sync(0xffffffffu, e2, o);
        e3 += __shfl_xor_sync(0xffffffffu, e3, o);
    }
    if (lane < 4) {
        const float v = (lane == 0) ? e0 : (lane == 1) ? e1 : (lane == 2) ? e2 : e3;
        out[b * DZ + j0 + lane] = v + bias;
    }
}

// ---------------------------------------------------------------------------
// Inputs: 0 query, 1 tokens, 2 q_w, 3 q_b, 4 k_w, 5 k_b (unused), 6 v_w, 7 v_b
// ---------------------------------------------------------------------------
extern "C" void kernel_launch(void* const* d_in, const int* in_sizes, int n_in,
                              void* d_out, int out_size)
{
    const float* query  = (const float*)d_in[0];
    const float* tokens = (const float*)d_in[1];
    const float* q_w    = (const float*)d_in[2];
    const float* q_b    = (const float*)d_in[3];
    const float* k_w    = (const float*)d_in[4];
    const float* v_w    = (const float*)d_in[6];
    const float* v_b    = (const float*)d_in[7];
    float* out = (float*)d_out;

    static bool attr_set = false;
    if (!attr_set) {
        cudaFuncSetAttribute(attn_pass,
                             cudaFuncAttributeMaxDynamicSharedMemorySize,
                             TOKBUF_BYTES);
        attr_set = true;
    }

    qtil_partial<<<BZ * NSLICE, 256>>>(query, q_w, q_b, k_w);

    cudaLaunchAttribute attrs[1];
    attrs[0].id = cudaLaunchAttributeProgrammaticStreamSerialization;
    attrs[0].val.programmaticStreamSerializationAllowed = 1;

    cudaLaunchConfig_t cfgB = {};
    cfgB.gridDim  = dim3(BZ * NCHUNK, 1, 1);
    cfgB.blockDim = dim3(256, 1, 1);
    cfgB.dynamicSmemBytes = TOKBUF_BYTES;
    cfgB.stream = 0;
    cfgB.attrs = attrs;
    cfgB.numAttrs = 1;
    cudaLaunchKernelEx(&cfgB, attn_pass, tokens);

    cudaLaunchConfig_t cfgC = {};
    cfgC.gridDim  = dim3(BZ * NSLICE, 1, 1);
    cfgC.blockDim = dim3(256, 1, 1);
    cfgC.dynamicSmemBytes = 0;
    cfgC.stream = 0;
    cfgC.attrs = attrs;
    cfgC.numAttrs = 1;
    cudaLaunchKernelEx(&cfgC, finalize, v_w, v_b, out);
}

// round 17
// speedup vs baseline: 1.1478x; 1.0006x over previous
#include <cuda_runtime.h>

#define BZ 32
#define MZ 8192
#define DZ 256
#define WARPS 8
#define NPART 9                       // blocks (ranges) per batch: one wave total
#define NSLICE 8
#define ATTN_SCALE 0.0625f            // 1/sqrt(256)
#define PF_TOKS 8                     // tokens prefetched per warp via cp.async
#define TOKBUF_BYTES (WARPS * PF_TOKS * DZ * 4)   // 64 KB dynamic smem

// Token-range boundaries per batch: 7x896 + 2x960 = 8192; all /64.
__constant__ int c_offs[NPART + 1] =
    {0, 896, 1792, 2688, 3584, 4480, 5376, 6272, 7232, 8192};

// Scratch (no allocations allowed in kernel_launch)
__device__ float  g_part[BZ * NSLICE * DZ];
__device__ float  g_pacc[BZ * NPART * DZ];
__device__ float2 g_pmz[BZ * NPART];

#define DOT8(xa, xb) ((xa).x*qa.x + (xa).y*qa.y + (xa).z*qa.z + (xa).w*qa.w \
                    + (xb).x*qb.x + (xb).y*qb.y + (xb).z*qb.z + (xb).w*qb.w)

#define DOT8T(xa, xb) ((xa).x*ta.x + (xa).y*ta.y + (xa).z*ta.z + (xa).w*ta.w \
                     + (xb).x*tb.x + (xb).y*tb.y + (xb).z*tb.z + (xb).w*tb.w)

// ---------------------------------------------------------------------------
// Kernel A: partial q~ per (batch, j-slice). Triggers PDL at entry so B
// launches concurrently and its cp.async prefetch overlaps A's execution.
// ---------------------------------------------------------------------------
__global__ void __launch_bounds__(256) qtil_partial(
    const float* __restrict__ query,
    const float* __restrict__ q_w,
    const float* __restrict__ q_b,
    const float* __restrict__ k_w)
{
    cudaTriggerProgrammaticLaunchCompletion();

    const int b    = blockIdx.x >> 3;
    const int s    = blockIdx.x & 7;
    const int tid  = threadIdx.x;
    const int w    = tid >> 5;
    const int lane = tid & 31;

    __shared__ float part[WARPS][DZ];

    const float4* qv = (const float4*)(query + (size_t)b * DZ);
    const float4 qa = qv[lane];
    const float4 qb = qv[32 + lane];

    const int j0 = s * 32 + w * 4;

    const float4* r0 = (const float4*)(q_w + (size_t)(j0 + 0) * DZ);
    const float4* r1 = (const float4*)(q_w + (size_t)(j0 + 1) * DZ);
    const float4* r2 = (const float4*)(q_w + (size_t)(j0 + 2) * DZ);
    const float4* r3 = (const float4*)(q_w + (size_t)(j0 + 3) * DZ);
    const float4* k0 = (const float4*)(k_w + (size_t)(j0 + 0) * DZ);
    const float4* k1 = (const float4*)(k_w + (size_t)(j0 + 1) * DZ);
    const float4* k2 = (const float4*)(k_w + (size_t)(j0 + 2) * DZ);
    const float4* k3 = (const float4*)(k_w + (size_t)(j0 + 3) * DZ);
    const float4 a0 = r0[lane], b0 = r0[32 + lane];
    const float4 a1 = r1[lane], b1 = r1[32 + lane];
    const float4 a2 = r2[lane], b2 = r2[32 + lane];
    const float4 a3 = r3[lane], b3 = r3[32 + lane];
    const float4 w0a = k0[lane], w0b = k0[32 + lane];
    const float4 w1a = k1[lane], w1b = k1[32 + lane];
    const float4 w2a = k2[lane], w2b = k2[32 + lane];
    const float4 w3a = k3[lane], w3b = k3[32 + lane];

    float d0 = DOT8(a0, b0);
    float d1 = DOT8(a1, b1);
    float d2 = DOT8(a2, b2);
    float d3 = DOT8(a3, b3);
    #pragma unroll
    for (int o = 16; o > 0; o >>= 1) {
        d0 += __shfl_xor_sync(0xffffffffu, d0, o);
        d1 += __shfl_xor_sync(0xffffffffu, d1, o);
        d2 += __shfl_xor_sync(0xffffffffu, d2, o);
        d3 += __shfl_xor_sync(0xffffffffu, d3, o);
    }
    const float qr0 = d0 + __ldg(q_b + j0 + 0);
    const float qr1 = d1 + __ldg(q_b + j0 + 1);
    const float qr2 = d2 + __ldg(q_b + j0 + 2);
    const float qr3 = d3 + __ldg(q_b + j0 + 3);

    float4 pa, pb;
    pa.x = qr0 * w0a.x + qr1 * w1a.x + qr2 * w2a.x + qr3 * w3a.x;
    pa.y = qr0 * w0a.y + qr1 * w1a.y + qr2 * w2a.y + qr3 * w3a.y;
    pa.z = qr0 * w0a.z + qr1 * w1a.z + qr2 * w2a.z + qr3 * w3a.z;
    pa.w = qr0 * w0a.w + qr1 * w1a.w + qr2 * w2a.w + qr3 * w3a.w;
    pb.x = qr0 * w0b.x + qr1 * w1b.x + qr2 * w2b.x + qr3 * w3b.x;
    pb.y = qr0 * w0b.y + qr1 * w1b.y + qr2 * w2b.y + qr3 * w3b.y;
    pb.z = qr0 * w0b.z + qr1 * w1b.z + qr2 * w2b.z + qr3 * w3b.z;
    pb.w = qr0 * w0b.w + qr1 * w1b.w + qr2 * w2b.w + qr3 * w3b.w;

    *(float4*)(&part[w][lane * 4])       = pa;
    *(float4*)(&part[w][128 + lane * 4]) = pb;
    __syncthreads();

    float acc = 0.0f;
    #pragma unroll
    for (int i = 0; i < WARPS; i++) acc += part[i][tid];
    g_part[(b * NSLICE + s) * DZ + tid] = acc;
}

// ---------------------------------------------------------------------------
// Kernel B: streaming pass, 288 blocks = one full wave at 2 blocks/SM.
// Block (b, r) streams tokens [c_offs[r], c_offs[r+1]) of batch b (warp-
// contiguous split, 8-token ILP groups) -> ONE (m, Z, acc) partial.
// PDL prologue: cp.async prefetch of group 0, then grid-sync on A.
// ---------------------------------------------------------------------------
#define ACC8(p, xa, xb)                                                    \
    do {                                                                   \
        aa.x += (p) * (xa).x; aa.y += (p) * (xa).y;                        \
        aa.z += (p) * (xa).z; aa.w += (p) * (xa).w;                        \
        ab.x += (p) * (xb).x; ab.y += (p) * (xb).y;                        \
        ab.z += (p) * (xb).z; ab.w += (p) * (xb).w;                        \
    } while (0)

#define LOADG8(g)                                                          \
    do {                                                                   \
        const float4* tp = base + (size_t)(g) * 8 * (DZ / 4);              \
        xa0 = __ldcs(tp + lane);        xb0 = __ldcs(tp + 32 + lane);      \
        xa1 = __ldcs(tp + 64 + lane);   xb1 = __ldcs(tp + 96 + lane);      \
        xa2 = __ldcs(tp + 128 + lane);  xb2 = __ldcs(tp + 160 + lane);     \
        xa3 = __ldcs(tp + 192 + lane);  xb3 = __ldcs(tp + 224 + lane);     \
        xa4 = __ldcs(tp + 256 + lane);  xb4 = __ldcs(tp + 288 + lane);     \
        xa5 = __ldcs(tp + 320 + lane);  xb5 = __ldcs(tp + 352 + lane);     \
        xa6 = __ldcs(tp + 384 + lane);  xb6 = __ldcs(tp + 416 + lane);     \
        xa7 = __ldcs(tp + 448 + lane);  xb7 = __ldcs(tp + 480 + lane);     \
    } while (0)

#define LOADS8()                                                           \
    do {                                                                   \
        xa0 = wbuf[lane];        xb0 = wbuf[32 + lane];                    \
        xa1 = wbuf[64 + lane];   xb1 = wbuf[96 + lane];                    \
        xa2 = wbuf[128 + lane];  xb2 = wbuf[160 + lane];                   \
        xa3 = wbuf[192 + lane];  xb3 = wbuf[224 + lane];                   \
        xa4 = wbuf[256 + lane];  xb4 = wbuf[288 + lane];                   \
        xa5 = wbuf[320 + lane];  xb5 = wbuf[352 + lane];                   \
        xa6 = wbuf[384 + lane];  xb6 = wbuf[416 + lane];                   \
        xa7 = wbuf[448 + lane];  xb7 = wbuf[480 + lane];                   \
    } while (0)

#define PROCG8()                                                           \
    do {                                                                   \
        float d0 = DOT8(xa0, xb0);                                         \
        float d1 = DOT8(xa1, xb1);                                         \
        float d2 = DOT8(xa2, xb2);                                         \
        float d3 = DOT8(xa3, xb3);                                         \
        float d4 = DOT8(xa4, xb4);                                         \
        float d5 = DOT8(xa5, xb5);                                         \
        float d6 = DOT8(xa6, xb6);                                         \
        float d7 = DOT8(xa7, xb7);                                         \
        _Pragma("unroll")                                                  \
        for (int o = 16; o > 0; o >>= 1) {                                 \
            d0 += __shfl_xor_sync(0xffffffffu, d0, o);                     \
            d1 += __shfl_xor_sync(0xffffffffu, d1, o);                     \
            d2 += __shfl_xor_sync(0xffffffffu, d2, o);                     \
            d3 += __shfl_xor_sync(0xffffffffu, d3, o);                     \
            d4 += __shfl_xor_sync(0xffffffffu, d4, o);                     \
            d5 += __shfl_xor_sync(0xffffffffu, d5, o);                     \
            d6 += __shfl_xor_sync(0xffffffffu, d6, o);                     \
            d7 += __shfl_xor_sync(0xffffffffu, d7, o);                     \
        }                                                                  \
        float gm = fmaxf(fmaxf(fmaxf(d0, d1), fmaxf(d2, d3)),              \
                         fmaxf(fmaxf(d4, d5), fmaxf(d6, d7)));             \
        if (gm > m) {                                                      \
            const float corr = __expf(m - gm);                             \
            z *= corr;                                                     \
            aa.x *= corr; aa.y *= corr; aa.z *= corr; aa.w *= corr;        \
            ab.x *= corr; ab.y *= corr; ab.z *= corr; ab.w *= corr;        \
            m = gm;                                                        \
        }                                                                  \
        const float p0 = __expf(d0 - m);                                   \
        const float p1 = __expf(d1 - m);                                   \
        const float p2 = __expf(d2 - m);                                   \
        const float p3 = __expf(d3 - m);                                   \
        const float p4 = __expf(d4 - m);                                   \
        const float p5 = __expf(d5 - m);                                   \
        const float p6 = __expf(d6 - m);                                   \
        const float p7 = __expf(d7 - m);                                   \
        z += ((p0 + p1) + (p2 + p3)) + ((p4 + p5) + (p6 + p7));            \
        ACC8(p0, xa0, xb0);                                                \
        ACC8(p1, xa1, xb1);                                                \
        ACC8(p2, xa2, xb2);                                                \
        ACC8(p3, xa3, xb3);                                                \
        ACC8(p4, xa4, xb4);                                                \
        ACC8(p5, xa5, xb5);                                                \
        ACC8(p6, xa6, xb6);                                                \
        ACC8(p7, xa7, xb7);                                                \
    } while (0)

__global__ void __launch_bounds__(256) attn_pass(const float* __restrict__ tokens)
{
    cudaTriggerProgrammaticLaunchCompletion();   // let C launch + prefetch v_w

    extern __shared__ float4 tokbuf[];           // 64 KB dynamic

    const int blk  = blockIdx.x;
    const int b    = blk / NPART;
    const int r    = blk - b * NPART;
    const int tid  = threadIdx.x;
    const int w    = tid >> 5;
    const int lane = tid & 31;

    __shared__ float  qtil_s[DZ];
    __shared__ float  sm_m[WARPS];
    __shared__ float  sm_z[WARPS];
    __shared__ float4 sm_acc[WARPS][64];

    const int t0      = c_offs[r];
    const int range   = c_offs[r + 1] - t0;      // 896 or 960
    const int wtoks   = range >> 3;              // tokens per warp
    const int ngroups = wtoks >> 3;              // 8-token groups per warp

    const float4* base = (const float4*)tokens
                       + ((size_t)b * MZ + t0 + w * wtoks) * (DZ / 4);

    // Register-free prefetch of this warp's first 8 tokens via cp.async;
    // DMA progresses while we wait on kernel A below.
    float4* wbuf = tokbuf + w * (PF_TOKS * DZ / 4);
    #pragma unroll
    for (int k2 = 0; k2 < (PF_TOKS * DZ / 4) / 32; k2++) {
        const int idx = lane + 32 * k2;
        const unsigned daddr = (unsigned)__cvta_generic_to_shared(wbuf + idx);
        asm volatile("cp.async.cg.shared.global [%0], [%1], 16;\n"
                     :: "r"(daddr), "l"(base + idx) : "memory");
    }
    asm volatile("cp.async.commit_group;\n" ::: "memory");

    cudaGridDependencySynchronize();             // wait for A's g_part

    {
        const float* gp = g_part + (size_t)b * NSLICE * DZ + tid;
        float t = 0.0f;
        #pragma unroll
        for (int s2 = 0; s2 < NSLICE; s2++) t += gp[s2 * DZ];
        qtil_s[tid] = t * ATTN_SCALE;
    }
    asm volatile("cp.async.wait_group 0;\n" ::: "memory");
    __syncthreads();

    const float4 qa = *(const float4*)(qtil_s + lane * 4);
    const float4 qb = *(const float4*)(qtil_s + 128 + lane * 4);

    float  m = -1e30f, z = 0.0f;
    float4 aa = make_float4(0.f, 0.f, 0.f, 0.f);
    float4 ab = make_float4(0.f, 0.f, 0.f, 0.f);

    float4 xa0, xb0, xa1, xb1, xa2, xb2, xa3, xb3;
    float4 xa4, xb4, xa5, xb5, xa6, xb6, xa7, xb7;

    LOADS8();                                    // group 0 from smem
    PROCG8();
    for (int g = 1; g < ngroups; g++) {
        LOADG8(g);
        PROCG8();
    }

    // Combine 8 warps -> one partial for this (b, r).
    if (lane == 0) { sm_m[w] = m; sm_z[w] = z; }
    sm_acc[w][lane]      = aa;
    sm_acc[w][32 + lane] = ab;
    __syncthreads();

    float Ms = sm_m[0];
    #pragma unroll
    for (int i = 1; i < WARPS; i++) Ms = fmaxf(Ms, sm_m[i]);

    const float* sa = (const float*)sm_acc;
    float accd = 0.0f;
    #pragma unroll
    for (int i = 0; i < WARPS; i++)
        accd += sa[i * DZ + tid] * __expf(sm_m[i] - Ms);
    g_pacc[((size_t)b * NPART + r) * DZ + tid] = accd;

    if (tid == 0) {
        float zt = 0.0f;
        #pragma unroll
        for (int i = 0; i < WARPS; i++) zt += sm_z[i] * __expf(sm_m[i] - Ms);
        g_pmz[b * NPART + r] = make_float2(Ms, zt);
    }
}

// ---------------------------------------------------------------------------
// Kernel C: PDL-launched; prefetches its v_w rows into registers BEFORE the
// grid sync, then merges 9 partials per batch and emits out[b,:].
// ---------------------------------------------------------------------------
__global__ void __launch_bounds__(256) finalize(
    const float* __restrict__ v_w,
    const float* __restrict__ v_b,
    float* __restrict__ out)
{
    const int b    = blockIdx.x >> 3;
    const int s    = blockIdx.x & 7;
    const int tid  = threadIdx.x;
    const int w    = tid >> 5;
    const int lane = tid & 31;

    __shared__ float  t_s[DZ];
    __shared__ float2 mz_s[NPART];

    const int j0 = s * 32 + w * 4;

    // Prefetch v_w rows + bias (independent of B) — overlaps B via PDL.
    const float4* r0 = (const float4*)(v_w + (size_t)(j0 + 0) * DZ);
    const float4* r1 = (const float4*)(v_w + (size_t)(j0 + 1) * DZ);
    const float4* r2 = (const float4*)(v_w + (size_t)(j0 + 2) * DZ);
    const float4* r3 = (const float4*)(v_w + (size_t)(j0 + 3) * DZ);
    const float4 a0 = r0[lane], b0 = r0[32 + lane];
    const float4 a1 = r1[lane], b1 = r1[32 + lane];
    const float4 a2 = r2[lane], b2 = r2[32 + lane];
    const float4 a3 = r3[lane], b3 = r3[32 + lane];
    const float bias = (lane < 4) ? __ldg(v_b + j0 + lane) : 0.0f;

    cudaGridDependencySynchronize();             // wait for B's partials

    if (tid < NPART) mz_s[tid] = g_pmz[b * NPART + tid];
    __syncthreads();

    float Mg = mz_s[0].x;
    #pragma unroll
    for (int i = 1; i < NPART; i++) Mg = fmaxf(Mg, mz_s[i].x);

    float Zg = 0.0f;
    #pragma unroll
    for (int i = 0; i < NPART; i++) Zg += mz_s[i].y * __expf(mz_s[i].x - Mg);
    const float inv = 1.0f / Zg;

    float td = 0.0f;
    #pragma unroll
    for (int i = 0; i < NPART; i++)
        td += g_pacc[((size_t)b * NPART + i) * DZ + tid] * __expf(mz_s[i].x - Mg);
    t_s[tid] = td * inv;
    __syncthreads();

    const float4 ta = *(const float4*)(t_s + lane * 4);
    const float4 tb = *(const float4*)(t_s + 128 + lane * 4);

    float e0 = DOT8T(a0, b0);
    float e1 = DOT8T(a1, b1);
    float e2 = DOT8T(a2, b2);
    float e3 = DOT8T(a3, b3);
    #pragma unroll
    for (int o = 16; o > 0; o >>= 1) {
        e0 += __shfl_xor_sync(0xffffffffu, e0, o);
        e1 += __shfl_xor_sync(0xffffffffu, e1, o);
        e2 += __shfl_xor_sync(0xffffffffu, e2, o);
        e3 += __shfl_xor_sync(0xffffffffu, e3, o);
    }
    if (lane < 4) {
        const float v = (lane == 0) ? e0 : (lane == 1) ? e1 : (lane == 2) ? e2 : e3;
        out[b * DZ + j0 + lane] = v + bias;
    }
}

// ---------------------------------------------------------------------------
// Inputs: 0 query, 1 tokens, 2 q_w, 3 q_b, 4 k_w, 5 k_b (unused), 6 v_w, 7 v_b
// ---------------------------------------------------------------------------
extern "C" void kernel_launch(void* const* d_in, const int* in_sizes, int n_in,
                              void* d_out, int out_size)
{
    const float* query  = (const float*)d_in[0];
    const float* tokens = (const float*)d_in[1];
    const float* q_w    = (const float*)d_in[2];
    const float* q_b    = (const float*)d_in[3];
    const float* k_w    = (const float*)d_in[4];
    const float* v_w    = (const float*)d_in[6];
    const float* v_b    = (const float*)d_in[7];
    float* out = (float*)d_out;

    static bool attr_set = false;
    if (!attr_set) {
        cudaFuncSetAttribute(attn_pass,
                             cudaFuncAttributeMaxDynamicSharedMemorySize,
                             TOKBUF_BYTES);
        attr_set = true;
    }

    qtil_partial<<<BZ * NSLICE, 256>>>(query, q_w, q_b, k_w);

    cudaLaunchAttribute attrs[1];
    attrs[0].id = cudaLaunchAttributeProgrammaticStreamSerialization;
    attrs[0].val.programmaticStreamSerializationAllowed = 1;

    cudaLaunchConfig_t cfgB = {};
    cfgB.gridDim  = dim3(BZ * NPART, 1, 1);
    cfgB.blockDim = dim3(256, 1, 1);
    cfgB.dynamicSmemBytes = TOKBUF_BYTES;
    cfgB.stream = 0;
    cfgB.attrs = attrs;
    cfgB.numAttrs = 1;
    cudaLaunchKernelEx(&cfgB, attn_pass, tokens);

    cudaLaunchConfig_t cfgC = {};
    cfgC.gridDim  = dim3(BZ * NSLICE, 1, 1);
    cfgC.blockDim = dim3(256, 1, 1);
    cfgC.dynamicSmemBytes = 0;
    cfgC.stream = 0;
    cfgC.attrs = attrs;
    cfgC.numAttrs = 1;
    cudaLaunchKernelEx(&cfgC, finalize, v_w, v_b, out);
}